// round 9
// baseline (speedup 1.0000x reference)
#include <cuda_runtime.h>
#include <math.h>

#define BB 16
#define CC 256
#define TT 4096
#define KK 5

#define WIN  166   // staged window per channel chunk: x[t0-16 .. t0+149]
#define WOFF 16

// Packed duplicated rp1 weights: g_wt2[(c*3 + d)*128 + c2] = (w,w) as f32x2.
__device__ unsigned long long g_wt2[CC * 3 * 128];

__global__ void transpose_rp1(const float* __restrict__ rp1_w) {
    int idx = blockIdx.x * blockDim.x + threadIdx.x;
    if (idx >= CC * 3 * 128) return;
    int c2 = idx & 127;
    int cd = idx >> 7;
    int d = cd % 3;
    int c = cd / 3;
    float w = rp1_w[(c2 * CC + c) * 3 + d];
    unsigned long long p;
    asm("mov.b64 %0, {%1, %2};" : "=l"(p) : "f"(w), "f"(w));
    g_wt2[idx] = p;
}

#define FFMA2(acc, a, b) asm("fma.rn.f32x2 %0, %1, %2, %0;" : "+l"(acc) : "l"(a), "l"(b))

__device__ __forceinline__ void unpackf2(unsigned long long v, float& lo, float& hi) {
    asm("mov.b64 {%0, %1}, %2;" : "=f"(lo), "=f"(hi) : "l"(v));
}

// ---------------------------------------------------------------------------
// Kernel 1 (round-7 structure + vectorized weight loads):
// offset/modulator convs + sigmoid + deformable sampling + diag einsum.
// Chunked windows (32 ch x WIN) re-staged per phase; 57KB smem -> 3 blocks/SM.
// s_w padded to stride 32 -> 8 broadcast LDS.128 per c-iter (was 30 scalar).
// s_dw padded to stride 8 -> 2 vector loads per c-iter (was 5 scalar).
// Numerics (values + fma order) bit-identical to rounds 5-7.
// Dynamic smem: s_w 256*32 | s_dw 256*8 | s_b 32*WIN = 15552 floats (62.2KB).
// ---------------------------------------------------------------------------
#define DEF_SMEM_FLOATS (CC * 32 + CC * 8 + 32 * WIN)

__global__ __launch_bounds__(128) void k_deform(
    const float* __restrict__ x,
    const float* __restrict__ ow, const float* __restrict__ ob,
    const float* __restrict__ mw, const float* __restrict__ mb,
    const float* __restrict__ weight,
    float* __restrict__ deformed)
{
    extern __shared__ float dsm_d[];
    float* s_w  = dsm_d;                     // [c][32]: j<15 offset, 15..29 mod, 30..31 pad
    float* s_dw = dsm_d + CC * 32;           // [c][8]: diag weights k=0..4, pad
    float* s_b  = dsm_d + CC * 32 + CC * 8;  // window [ci][WIN]

    const int tid = threadIdx.x;
    const int t0 = blockIdx.x * 128;
    const int b = blockIdx.y;
    const float* xb = x + (size_t)b * CC * TT;

    // conv weights -> smem (padded stride 32)
    for (int i = tid; i < CC * 32; i += 128) {
        int c = i >> 5;
        int j = i & 31;
        float v = 0.f;
        if (j < 15) {
            int k = j / 3, d = j - k * 3;
            v = ow[k * (CC * 3) + c * 3 + d];
        } else if (j < 30) {
            int jj = j - 15;
            int k = jj / 3, d = jj - k * 3;
            v = mw[k * (CC * 3) + c * 3 + d];
        }
        s_w[i] = v;
    }
    // diag weights -> smem (padded stride 8)
    for (int i = tid; i < CC * 8; i += 128) {
        int c = i >> 3;
        int k = i & 7;
        s_dw[i] = (k < KK) ? __ldg(weight + ((size_t)c * CC + c) * KK + k) : 0.f;
    }

    float offa[KK] = {0.f, 0.f, 0.f, 0.f, 0.f};
    float moda[KK] = {0.f, 0.f, 0.f, 0.f, 0.f};

    // Phase A: 10-channel conv (chunk-folded fp32 accumulation — frozen order)
    for (int cc = 0; cc < CC; cc += 32) {
        __syncthreads();
        for (int idx = tid; idx < 32 * WIN; idx += 128) {
            int ci = idx / WIN;
            int u = idx - ci * WIN;
            int tg = t0 - WOFF + u;
            s_b[idx] = (tg >= 0 && tg < TT) ? __ldg(xb + (size_t)(cc + ci) * TT + tg) : 0.f;
        }
        __syncthreads();
        float offc[KK] = {0.f, 0.f, 0.f, 0.f, 0.f};
        float modc[KK] = {0.f, 0.f, 0.f, 0.f, 0.f};
        #pragma unroll 1
        for (int ci = 0; ci < 32; ci++) {
            // broadcast-load 30 weights as 8 LDS.128 into registers
            const float4* w4 = reinterpret_cast<const float4*>(s_w + (cc + ci) * 32);
            float wv[32];
            #pragma unroll
            for (int q = 0; q < 8; q++) {
                float4 v = w4[q];
                wv[4 * q + 0] = v.x;
                wv[4 * q + 1] = v.y;
                wv[4 * q + 2] = v.z;
                wv[4 * q + 3] = v.w;
            }
            const float* xs = s_b + ci * WIN + tid + (WOFF - 1);
            float x0 = xs[0];
            float x1 = xs[1];
            float x2 = xs[2];
            #pragma unroll
            for (int k = 0; k < KK; k++) {
                offc[k] += x0 * wv[k * 3 + 0] + x1 * wv[k * 3 + 1] + x2 * wv[k * 3 + 2];
                modc[k] += x0 * wv[15 + k * 3 + 0] + x1 * wv[15 + k * 3 + 1] + x2 * wv[15 + k * 3 + 2];
            }
        }
        #pragma unroll
        for (int k = 0; k < KK; k++) { offa[k] += offc[k]; moda[k] += modc[k]; }
    }

    // positions / interp weights (exact fp32 — frozen)
    const int t = t0 + tid;
    float mf[KK], mc[KK];
    int pfi[KK], pci[KK];
    #pragma unroll
    for (int k = 0; k < KK; k++) {
        float off = offa[k] + __ldg(ob + k);
        float z = moda[k] + __ldg(mb + k);
        float mod = 1.f / (1.f + expf(-z));
        float pos = (float)(t + k - 2) + off;
        pos = fminf(fmaxf(pos, 0.f), (float)(TT - 1));
        float pf = floorf(pos);
        float pc = ceilf(pos);
        mf[k] = (pc - pos) * mod;
        mc[k] = (pos - pf) * mod;
        pfi[k] = (int)pf;
        pci[k] = (int)pc;
    }

    // window indices + warp vote
    int idxf[KK], idxc[KK];
    bool allin = true;
    #pragma unroll
    for (int k = 0; k < KK; k++) {
        idxf[k] = pfi[k] - (t0 - WOFF);
        idxc[k] = pci[k] - (t0 - WOFF);
        allin = allin && ((unsigned)idxf[k] < (unsigned)WIN) && ((unsigned)idxc[k] < (unsigned)WIN);
    }
    const bool fast = __all_sync(0xffffffffu, allin);

    // Phase B: sample + diag einsum, chunk-staged windows
    float* db = deformed + (size_t)b * CC * TT;
    for (int cc = 0; cc < CC; cc += 32) {
        __syncthreads();
        for (int idx = tid; idx < 32 * WIN; idx += 128) {
            int ci = idx / WIN;
            int u = idx - ci * WIN;
            int tg = t0 - WOFF + u;
            s_b[idx] = (tg >= 0 && tg < TT) ? __ldg(xb + (size_t)(cc + ci) * TT + tg) : 0.f;
        }
        __syncthreads();
        if (fast) {
            #pragma unroll 2
            for (int ci = 0; ci < 32; ci++) {
                const float* xs = s_b + ci * WIN;
                const float4* d4 = reinterpret_cast<const float4*>(s_dw + (cc + ci) * 8);
                float4 dv0 = d4[0];
                float dv4 = s_dw[(cc + ci) * 8 + 4];
                float dwv[KK] = {dv0.x, dv0.y, dv0.z, dv0.w, dv4};
                float acc = 0.f;
                #pragma unroll
                for (int k = 0; k < KK; k++) {
                    float s = xs[idxf[k]] * mf[k] + xs[idxc[k]] * mc[k];
                    acc = fmaf(s, dwv[k], acc);
                }
                db[(size_t)(cc + ci) * TT + t] = acc;
            }
        } else {
            #pragma unroll 1
            for (int ci = 0; ci < 32; ci++) {
                const float* xc = xb + (size_t)(cc + ci) * TT;
                const float* dwc = s_dw + (cc + ci) * 8;
                float acc = 0.f;
                #pragma unroll
                for (int k = 0; k < KK; k++) {
                    float s = __ldg(xc + pfi[k]) * mf[k] + __ldg(xc + pci[k]) * mc[k];
                    acc = fmaf(s, dwc[k], acc);
                }
                db[(size_t)(cc + ci) * TT + t] = acc;
            }
        }
    }
}

// ---------------------------------------------------------------------------
// Kernel 2: UNCHANGED (measured at 98.8% of the scalar fp32 FMA ceiling;
// f32x2 is being split by ptxas — tensor-core rewrite needs SASS evidence
// first). Dynamic smem 69632 B.
// ---------------------------------------------------------------------------
#define REC_SMEM_FLOATS (CC * 32 + CC * 36)

__global__ __launch_bounds__(128) void k_recover(
    const float* __restrict__ deformed,
    const float* __restrict__ rp1_b,
    const float* __restrict__ rp2_w,
    const float* __restrict__ rp2_b,
    float* __restrict__ recovery)
{
    extern __shared__ float dsm[];
    float* sA = dsm;
    float* sB = dsm + CC * 32;
    __shared__ float sp[4 * 33];

    const int tid = threadIdx.x;
    const int t0 = blockIdx.x * 32;
    const int b = blockIdx.y;
    const float* db = deformed + (size_t)b * CC * TT;

    for (int idx = tid; idx < CC * 34; idx += 128) {
        int c = idx / 34;
        int u = idx - c * 34;
        int tg = t0 + u - 1;
        float v = (tg >= 0 && tg < TT) ? db[(size_t)c * TT + tg] : 0.f;
        sB[c * 36 + u] = v;
        int vv = u - 1;
        if (vv >= 0 && vv < 32) sA[c * 32 + vv] = v;
    }
    __syncthreads();

    unsigned long long acc2[16];
    #pragma unroll
    for (int j = 0; j < 16; j++) acc2[j] = 0ull;

    const int c2 = tid;
    const unsigned long long* W = g_wt2 + c2;
    unsigned long long w0n = __ldg(W);
    unsigned long long w1n = __ldg(W + 128);
    unsigned long long w2n = __ldg(W + 256);

    #pragma unroll 1
    for (int c = 0; c < CC; c++) {
        unsigned long long w0p = w0n, w1p = w1n, w2p = w2n;
        if (c < CC - 1) {
            const unsigned long long* Wn = W + (c + 1) * 384;
            w0n = __ldg(Wn);
            w1n = __ldg(Wn + 128);
            w2n = __ldg(Wn + 256);
        }
        const ulonglong2* A128 = reinterpret_cast<const ulonglong2*>(sA + c * 32);
        const ulonglong2* B128 = reinterpret_cast<const ulonglong2*>(sB + c * 36);
        ulonglong2 bq = B128[0];
        #pragma unroll
        for (int q = 0; q < 8; q++) {
            ulonglong2 aq = A128[q];
            ulonglong2 bq1 = B128[q + 1];
            FFMA2(acc2[2 * q], bq.x, w0p);
            FFMA2(acc2[2 * q], aq.x, w1p);
            FFMA2(acc2[2 * q], bq.y, w2p);
            FFMA2(acc2[2 * q + 1], bq.y, w0p);
            FFMA2(acc2[2 * q + 1], aq.y, w1p);
            FFMA2(acc2[2 * q + 1], bq1.x, w2p);
            bq = bq1;
        }
    }

    const float b1 = __ldg(rp1_b + c2);
    const float w2c = __ldg(rp2_w + c2);

    __syncthreads();
    float* sc = dsm;
    #pragma unroll
    for (int j = 0; j < 16; j++) {
        float h0, h1;
        unpackf2(acc2[j], h0, h1);
        h0 = fmaxf(h0 + b1, 0.f) * w2c;
        h1 = fmaxf(h1 + b1, 0.f) * w2c;
        sc[(2 * j) * 129 + c2] = h0;
        sc[(2 * j + 1) * 129 + c2] = h1;
    }
    __syncthreads();

    {
        int tl = tid & 31;
        int w = tid >> 5;
        const float* row = sc + tl * 129 + w * 32;
        float s = 0.f;
        #pragma unroll
        for (int i = 0; i < 32; i++) s += row[i];
        sp[w * 33 + tl] = s;
    }
    __syncthreads();

    if (tid < 32) {
        float r = sp[tid] + sp[33 + tid] + sp[66 + tid] + sp[99 + tid] + __ldg(rp2_b);
        recovery[(size_t)b * TT + t0 + tid] = r;
    }
}

// ---------------------------------------------------------------------------
extern "C" void kernel_launch(void* const* d_in, const int* in_sizes, int n_in,
                              void* d_out, int out_size) {
    const float* x     = (const float*)d_in[0];
    const float* ow    = (const float*)d_in[1];
    const float* ob    = (const float*)d_in[2];
    const float* mw    = (const float*)d_in[3];
    const float* mb    = (const float*)d_in[4];
    const float* wgt   = (const float*)d_in[5];
    const float* rp1_w = (const float*)d_in[6];
    const float* rp1_b = (const float*)d_in[7];
    const float* rp2_w = (const float*)d_in[8];
    const float* rp2_b = (const float*)d_in[9];

    float* out = (float*)d_out;
    float* deformed = out;                              // (B, C, T)
    float* recovery = out + (size_t)BB * CC * TT;       // (B, T)

    cudaFuncSetAttribute(k_deform, cudaFuncAttributeMaxDynamicSharedMemorySize,
                         DEF_SMEM_FLOATS * (int)sizeof(float));
    cudaFuncSetAttribute(k_recover, cudaFuncAttributeMaxDynamicSharedMemorySize,
                         REC_SMEM_FLOATS * (int)sizeof(float));

    k_deform<<<dim3(TT / 128, BB), 128, DEF_SMEM_FLOATS * sizeof(float)>>>(
        x, ow, ob, mw, mb, wgt, deformed);
    transpose_rp1<<<(CC * 3 * 128 + 255) / 256, 256>>>(rp1_w);
    k_recover<<<dim3(TT / 32, BB), 128, REC_SMEM_FLOATS * sizeof(float)>>>(
        deformed, rp1_b, rp2_w, rp2_b, recovery);
}

// round 11
// speedup vs baseline: 1.5412x; 1.5412x over previous
#include <cuda_runtime.h>
#include <math.h>

#define BB 16
#define CC 256
#define TT 4096
#define KK 5

#define WIN  166
#define WOFF 16

// fp32 -> tf32 RNE rounding (bit-exact round-to-nearest-even on low 13 bits)
__device__ __forceinline__ float tf32r(float x) {
    unsigned int u = __float_as_uint(x);
    u += 0xFFFu + ((u >> 13) & 1u);
    u &= ~0x1FFFu;
    return __uint_as_float(u);
}

// ===========================================================================
// Precomputed B fragments for mma.m16n8k8.row.col tf32.
// K = 768 (k = c*3 + d), N = 128 (c2). Fragment order:
//   g_wfrag[((((p*96 + kc)*2 + wn)*8 + nt)*32 + lane)*2 + r]
// p: 0=hi 1=lo; kc: k-chunk (8 k); wn: N-half; nt: n8 tile; lane; r: b0/b1.
// Per PTX mapping: b_r = W[n = wn*64+nt*8+groupID][k = kc*8+tig+r*4],
// tig = lane&3, groupID = lane>>2.
// ===========================================================================
__device__ __align__(16) float g_wfrag[2 * 96 * 2 * 8 * 32 * 2];

__global__ void prep_wfrag(const float* __restrict__ rp1_w) {
    int e = blockIdx.x * blockDim.x + threadIdx.x;
    if (e >= 2 * 96 * 2 * 8 * 32 * 2) return;
    int r2   = e & 1;
    int lane = (e >> 1) & 31;
    int nt   = (e >> 6) & 7;
    int wn   = (e >> 9) & 1;
    int kc   = (e >> 10) % 96;
    int p    = (e >> 10) / 96;
    int tig = lane & 3;
    int g   = lane >> 2;
    int k = kc * 8 + tig + r2 * 4;
    int c = k / 3;
    int d = k - 3 * c;
    int n = wn * 64 + nt * 8 + g;
    float w = __ldg(rp1_w + (n * CC + c) * 3 + d);
    float hi = tf32r(w);
    g_wfrag[e] = p ? tf32r(w - hi) : hi;
}

// m16n8k8 tf32 mma (family-portable PTX; no sm_103a-only features)
__device__ __forceinline__ void mma8(float* d, const unsigned* a, unsigned b0, unsigned b1) {
    asm volatile(
        "mma.sync.aligned.m16n8k8.row.col.f32.tf32.tf32.f32 "
        "{%0,%1,%2,%3},{%4,%5,%6,%7},{%8,%9},{%0,%1,%2,%3};"
        : "+f"(d[0]), "+f"(d[1]), "+f"(d[2]), "+f"(d[3])
        : "r"(a[0]), "r"(a[1]), "r"(a[2]), "r"(a[3]), "r"(b0), "r"(b1));
}

// ===========================================================================
// Kernel 1: round-7 k_deform VERBATIM (176.3us measured; numerics frozen)
// ===========================================================================
#define DEF_SMEM_FLOATS (CC * 30 + CC * KK + 32 * WIN)

__global__ __launch_bounds__(128) void k_deform(
    const float* __restrict__ x,
    const float* __restrict__ ow, const float* __restrict__ ob,
    const float* __restrict__ mw, const float* __restrict__ mb,
    const float* __restrict__ weight,
    float* __restrict__ deformed)
{
    extern __shared__ float dsm_d[];
    float* s_w  = dsm_d;
    float* s_dw = dsm_d + CC * 30;
    float* s_b  = dsm_d + CC * 30 + CC * KK;

    const int tid = threadIdx.x;
    const int t0 = blockIdx.x * 128;
    const int b = blockIdx.y;
    const float* xb = x + (size_t)b * CC * TT;

    for (int i = tid; i < CC * 30; i += 128) {
        int c = i / 30;
        int j = i - c * 30;
        float v;
        if (j < 15) {
            int k = j / 3, d = j - k * 3;
            v = ow[k * (CC * 3) + c * 3 + d];
        } else {
            int jj = j - 15;
            int k = jj / 3, d = jj - k * 3;
            v = mw[k * (CC * 3) + c * 3 + d];
        }
        s_w[i] = v;
    }

    float offa[KK] = {0.f, 0.f, 0.f, 0.f, 0.f};
    float moda[KK] = {0.f, 0.f, 0.f, 0.f, 0.f};

    for (int cc = 0; cc < CC; cc += 32) {
        __syncthreads();
        for (int idx = tid; idx < 32 * WIN; idx += 128) {
            int ci = idx / WIN;
            int u = idx - ci * WIN;
            int tg = t0 - WOFF + u;
            s_b[idx] = (tg >= 0 && tg < TT) ? __ldg(xb + (size_t)(cc + ci) * TT + tg) : 0.f;
        }
        __syncthreads();
        float offc[KK] = {0.f, 0.f, 0.f, 0.f, 0.f};
        float modc[KK] = {0.f, 0.f, 0.f, 0.f, 0.f};
        #pragma unroll 1
        for (int ci = 0; ci < 32; ci++) {
            const float* wrow = s_w + (cc + ci) * 30;
            const float* xs = s_b + ci * WIN + tid + (WOFF - 1);
            float x0 = xs[0];
            float x1 = xs[1];
            float x2 = xs[2];
            #pragma unroll
            for (int k = 0; k < KK; k++) {
                offc[k] += x0 * wrow[k * 3 + 0] + x1 * wrow[k * 3 + 1] + x2 * wrow[k * 3 + 2];
                modc[k] += x0 * wrow[15 + k * 3 + 0] + x1 * wrow[15 + k * 3 + 1] + x2 * wrow[15 + k * 3 + 2];
            }
        }
        #pragma unroll
        for (int k = 0; k < KK; k++) { offa[k] += offc[k]; moda[k] += modc[k]; }
    }

    const int t = t0 + tid;
    float mf[KK], mc[KK];
    int pfi[KK], pci[KK];
    #pragma unroll
    for (int k = 0; k < KK; k++) {
        float off = offa[k] + __ldg(ob + k);
        float z = moda[k] + __ldg(mb + k);
        float mod = 1.f / (1.f + expf(-z));
        float pos = (float)(t + k - 2) + off;
        pos = fminf(fmaxf(pos, 0.f), (float)(TT - 1));
        float pf = floorf(pos);
        float pc = ceilf(pos);
        mf[k] = (pc - pos) * mod;
        mc[k] = (pos - pf) * mod;
        pfi[k] = (int)pf;
        pci[k] = (int)pc;
    }

    int idxf[KK], idxc[KK];
    bool allin = true;
    #pragma unroll
    for (int k = 0; k < KK; k++) {
        idxf[k] = pfi[k] - (t0 - WOFF);
        idxc[k] = pci[k] - (t0 - WOFF);
        allin = allin && ((unsigned)idxf[k] < (unsigned)WIN) && ((unsigned)idxc[k] < (unsigned)WIN);
    }
    const bool fast = __all_sync(0xffffffffu, allin);

    __syncthreads();
    for (int i = tid; i < CC * KK; i += 128) {
        int c = i / KK;
        int k = i - c * KK;
        s_dw[i] = __ldg(weight + ((size_t)c * CC + c) * KK + k);
    }

    float* db = deformed + (size_t)b * CC * TT;
    for (int cc = 0; cc < CC; cc += 32) {
        __syncthreads();
        for (int idx = tid; idx < 32 * WIN; idx += 128) {
            int ci = idx / WIN;
            int u = idx - ci * WIN;
            int tg = t0 - WOFF + u;
            s_b[idx] = (tg >= 0 && tg < TT) ? __ldg(xb + (size_t)(cc + ci) * TT + tg) : 0.f;
        }
        __syncthreads();
        if (fast) {
            #pragma unroll 2
            for (int ci = 0; ci < 32; ci++) {
                const float* xs = s_b + ci * WIN;
                const float* dwc = s_dw + (cc + ci) * KK;
                float acc = 0.f;
                #pragma unroll
                for (int k = 0; k < KK; k++) {
                    float s = xs[idxf[k]] * mf[k] + xs[idxc[k]] * mc[k];
                    acc = fmaf(s, dwc[k], acc);
                }
                db[(size_t)(cc + ci) * TT + t] = acc;
            }
        } else {
            #pragma unroll 1
            for (int ci = 0; ci < 32; ci++) {
                const float* xc = xb + (size_t)(cc + ci) * TT;
                const float* dwc = s_dw + (cc + ci) * KK;
                float acc = 0.f;
                #pragma unroll
                for (int k = 0; k < KK; k++) {
                    float s = __ldg(xc + pfi[k]) * mf[k] + __ldg(xc + pci[k]) * mc[k];
                    acc = fmaf(s, dwc[k], acc);
                }
                db[(size_t)(cc + ci) * TT + t] = acc;
            }
        }
    }
}

// ===========================================================================
// Kernel 2 (NEW): rp1 conv as 3xTF32 mma.sync GEMM + fused relu / rp2 dot.
// CTA: 256 threads (8 warps) = 128 t x 128 c2 tile; grid 512.
// Warp (wm=wid&3, wn=wid>>2): rows [wm*32, wm*32+32), cols [wn*64, wn*64+64).
// K = 768 staged in 4 c-groups of 64 channels (24 k-chunks each).
// ===========================================================================
__global__ __launch_bounds__(256, 2) void k_recover2(
    const float* __restrict__ deformed,
    const float* __restrict__ rp1_b,
    const float* __restrict__ rp2_w,
    const float* __restrict__ rp2_b,
    float* __restrict__ recovery)
{
    __shared__ float sdef[64 * 132];   // [j][u]: deformed[cg*64+j][t0-1+u], u=0..129
    __shared__ float sp[2][128];

    const int tid = threadIdx.x;
    const int wid = tid >> 5;
    const int lane = tid & 31;
    const int wm = wid & 3;
    const int wn = wid >> 2;
    const int tig = lane & 3;
    const int g = lane >> 2;

    const int bx = blockIdx.x;
    const int b  = bx >> 5;
    const int t0 = (bx & 31) << 7;
    const float* db = deformed + (size_t)b * CC * TT;
    const uint2* Wf = reinterpret_cast<const uint2*>(g_wfrag);

    float dacc[2][8][4];
    #pragma unroll
    for (int mt = 0; mt < 2; mt++)
        #pragma unroll
        for (int nt = 0; nt < 8; nt++)
            #pragma unroll
            for (int r = 0; r < 4; r++) dacc[mt][nt][r] = 0.f;

    const int ttb = wm * 32 + g;   // base row (mt adds 16, +8 for odd regs)

    for (int cg = 0; cg < 4; cg++) {
        __syncthreads();
        for (int i = tid; i < 64 * 130; i += 256) {
            int j = i / 130;
            int u = i - j * 130;
            int tg = t0 - 1 + u;
            sdef[j * 132 + u] = (tg >= 0 && tg < TT)
                ? __ldg(db + (size_t)(cg * 64 + j) * TT + tg) : 0.f;
        }
        __syncthreads();

        #pragma unroll 1
        for (int kcl = 0; kcl < 24; kcl++) {
            const int kc = cg * 24 + kcl;
            // A-side indices for this k-chunk (shared across mt)
            const int kk0 = kc * 8 + tig;
            const int kk1 = kk0 + 4;
            const int c0 = kk0 / 3, d0 = kk0 - 3 * c0, j0 = c0 - cg * 64;
            const int c1 = kk1 / 3, d1 = kk1 - 3 * c1, j1 = c1 - cg * 64;

            unsigned ahi[2][4], alo[2][4];
            #pragma unroll
            for (int mt = 0; mt < 2; mt++) {
                const int tt = ttb + mt * 16;
                float v0 = sdef[j0 * 132 + tt + d0];
                float v1 = sdef[j0 * 132 + tt + 8 + d0];
                float v2 = sdef[j1 * 132 + tt + d1];
                float v3 = sdef[j1 * 132 + tt + 8 + d1];
                float h0 = tf32r(v0), h1 = tf32r(v1), h2 = tf32r(v2), h3 = tf32r(v3);
                ahi[mt][0] = __float_as_uint(h0);
                ahi[mt][1] = __float_as_uint(h1);
                ahi[mt][2] = __float_as_uint(h2);
                ahi[mt][3] = __float_as_uint(h3);
                alo[mt][0] = __float_as_uint(tf32r(v0 - h0));
                alo[mt][1] = __float_as_uint(tf32r(v1 - h1));
                alo[mt][2] = __float_as_uint(tf32r(v2 - h2));
                alo[mt][3] = __float_as_uint(tf32r(v3 - h3));
            }

            const int fb = ((kc * 2 + wn) * 8) * 32 + lane;        // hi base
            const int fl = (((96 + kc) * 2 + wn) * 8) * 32 + lane; // lo base
            #pragma unroll
            for (int nt = 0; nt < 8; nt++) {
                uint2 bh = __ldg(Wf + fb + nt * 32);
                uint2 bl = __ldg(Wf + fl + nt * 32);
                #pragma unroll
                for (int mt = 0; mt < 2; mt++) {
                    mma8(dacc[mt][nt], ahi[mt], bh.x, bh.y);
                    mma8(dacc[mt][nt], ahi[mt], bl.x, bl.y);
                    mma8(dacc[mt][nt], alo[mt], bh.x, bh.y);
                }
            }
        }
    }

    // Epilogue: relu(h + b1) * w2, reduce over c2
    #pragma unroll
    for (int mt = 0; mt < 2; mt++) {
        float s0 = 0.f, s8 = 0.f;
        #pragma unroll
        for (int nt = 0; nt < 8; nt++) {
            int c2 = wn * 64 + nt * 8 + tig * 2;
            float b1a = __ldg(rp1_b + c2),     b1b = __ldg(rp1_b + c2 + 1);
            float w2a = __ldg(rp2_w + c2),     w2b = __ldg(rp2_w + c2 + 1);
            s0 += fmaxf(dacc[mt][nt][0] + b1a, 0.f) * w2a
                + fmaxf(dacc[mt][nt][1] + b1b, 0.f) * w2b;
            s8 += fmaxf(dacc[mt][nt][2] + b1a, 0.f) * w2a
                + fmaxf(dacc[mt][nt][3] + b1b, 0.f) * w2b;
        }
        s0 += __shfl_xor_sync(0xffffffffu, s0, 1);
        s0 += __shfl_xor_sync(0xffffffffu, s0, 2);
        s8 += __shfl_xor_sync(0xffffffffu, s8, 1);
        s8 += __shfl_xor_sync(0xffffffffu, s8, 2);
        if (tig == 0) {
            sp[wn][wm * 32 + mt * 16 + g] = s0;
            sp[wn][wm * 32 + mt * 16 + g + 8] = s8;
        }
    }
    __syncthreads();

    if (tid < 128) {
        recovery[(size_t)b * TT + t0 + tid] = sp[0][tid] + sp[1][tid] + __ldg(rp2_b);
    }
}

// ---------------------------------------------------------------------------
extern "C" void kernel_launch(void* const* d_in, const int* in_sizes, int n_in,
                              void* d_out, int out_size) {
    const float* x     = (const float*)d_in[0];
    const float* ow    = (const float*)d_in[1];
    const float* ob    = (const float*)d_in[2];
    const float* mw    = (const float*)d_in[3];
    const float* mb    = (const float*)d_in[4];
    const float* wgt   = (const float*)d_in[5];
    const float* rp1_w = (const float*)d_in[6];
    const float* rp1_b = (const float*)d_in[7];
    const float* rp2_w = (const float*)d_in[8];
    const float* rp2_b = (const float*)d_in[9];

    float* out = (float*)d_out;
    float* deformed = out;                              // (B, C, T)
    float* recovery = out + (size_t)BB * CC * TT;       // (B, T)

    cudaFuncSetAttribute(k_deform, cudaFuncAttributeMaxDynamicSharedMemorySize,
                         DEF_SMEM_FLOATS * (int)sizeof(float));

    prep_wfrag<<<(2 * 96 * 2 * 8 * 32 * 2 + 255) / 256, 256>>>(rp1_w);
    k_deform<<<dim3(TT / 128, BB), 128, DEF_SMEM_FLOATS * sizeof(float)>>>(
        x, ow, ob, mw, mb, wgt, deformed);
    k_recover2<<<512, 256>>>(deformed, rp1_b, rp2_w, rp2_b, recovery);
}